// round 8
// baseline (speedup 1.0000x reference)
#include <cuda_runtime.h>
#include <cuda_bf16.h>

typedef unsigned int u32;
typedef unsigned short u16;
typedef unsigned char u8;

// Problem constants
#define NB   8
#define NT   4096
#define ND   512
#define NDI  1024
#define NM   (NB * NT)   // 32768 rows (B*T)

// fp8 static scales (powers of two)
#define SX   8.0f      // x            -> fp8
#define SW   64.0f     // all weights  -> fp8
#define SA   128.0f    // conv outputs -> fp8 (folded into conv weights/bias)
#define SY   256.0f    // Y            -> fp8

// ---------------------------------------------------------------------------
// Scratch (static __device__ arrays; no allocations allowed)
// ---------------------------------------------------------------------------
__device__ u8  g_x8 [NM * ND];          // x fp8 (*SX)
__device__ u8  g_wi8[2 * NDI * ND];     // in_proj_w fp8 (*SW)
__device__ u8  g_wpf8[NDI * NDI];       // proj_fwd_w fp8 (*SW)
__device__ u8  g_wpb8[NDI * NDI];       // proj_bwd_w fp8 (*SW)
__device__ u8  g_wo8[ND * NDI];         // out_proj_w fp8 (*SW)
__device__ u8  g_Af8[NM * NDI];         // conv fwd out fp8 (*SA)
__device__ u8  g_Ab8[NM * NDI];         // conv bwd out fp8 (*SA)
__device__ u8  g_Y8 [NM * NDI];         // gated mixer out fp8 (*SY)
__device__ float g_cwf[7 * NDI];        // conv fwd w, [tap][chan] fp32 * SA
__device__ float g_cwb[7 * NDI];        // conv bwd w, [tap][chan] fp32 * SA
__device__ __nv_bfloat16 g_Xp[NM * NDI];  // x_proj bf16
__device__ __nv_bfloat16 g_Z [NM * NDI];  // z bf16
__device__ __nv_bfloat16 g_Sf[NM * NDI];  // silu(proj_fwd + bias) bf16
__device__ float g_H [NM * ND];           // residual + out_proj (fp32)

__device__ __forceinline__ float silu_f(float x) {
    return x / (1.0f + __expf(-x));
}

__device__ __forceinline__ u32 smem_u32(const void* p) {
    u32 a;
    asm("{ .reg .u64 t; cvta.to.shared.u64 t, %1; cvt.u32.u64 %0, t; }"
        : "=r"(a) : "l"(p));
    return a;
}

// pack 4 floats -> 4 e4m3 bytes (byte i = f_i)
__device__ __forceinline__ u32 pack_e4m3_4(float f0, float f1, float f2, float f3) {
    u32 r;
    asm("{\n\t.reg .b16 lo, hi;\n\t"
        "cvt.rn.satfinite.e4m3x2.f32 lo, %2, %1;\n\t"
        "cvt.rn.satfinite.e4m3x2.f32 hi, %4, %3;\n\t"
        "mov.b32 %0, {lo, hi};\n\t}"
        : "=r"(r) : "f"(f0), "f"(f1), "f"(f2), "f"(f3));
    return r;
}
// pack 2 floats -> 2 e4m3 bytes in u16
__device__ __forceinline__ u16 pack_e4m3_2(float f0, float f1) {
    u16 r;
    asm("cvt.rn.satfinite.e4m3x2.f32 %0, %2, %1;" : "=h"(r) : "f"(f0), "f"(f1));
    return r;
}

// ---------------------------------------------------------------------------
// PTX primitives: cp.async, ldmatrix, fp8 mma (compute_103-base legal)
// ---------------------------------------------------------------------------
__device__ __forceinline__ void cpa16(u32 s, const void* g) {
    asm volatile("cp.async.cg.shared.global [%0], [%1], 16;" :: "r"(s), "l"(g));
}
#define CP_COMMIT()  asm volatile("cp.async.commit_group;" ::: "memory")
#define CP_WAIT(N)   asm volatile("cp.async.wait_group %0;" :: "n"(N) : "memory")

#define LDSM4(r0, r1, r2, r3, addr) \
    asm volatile("ldmatrix.sync.aligned.m8n8.x4.shared.b16 {%0,%1,%2,%3}, [%4];" \
        : "=r"(r0), "=r"(r1), "=r"(r2), "=r"(r3) : "r"(addr))

#define MMAFP8(c, a, b) \
    asm volatile("mma.sync.aligned.m16n8k32.row.col.f32.e4m3.e4m3.f32 " \
        "{%0,%1,%2,%3}, {%4,%5,%6,%7}, {%8,%9}, {%0,%1,%2,%3};" \
        : "+f"((c)[0]), "+f"((c)[1]), "+f"((c)[2]), "+f"((c)[3]) \
        : "r"((a)[0]), "r"((a)[1]), "r"((a)[2]), "r"((a)[3]), \
          "r"((b)[0]), "r"((b)[1]))

// ---------------------------------------------------------------------------
// FP8 warp-MMA GEMM: C[m,n] = sum_k A[m,k]*W[n,k], e4m3 in, fp32 accum.
// BM=BN=128, BK=128 fp8 (128B row), 256 threads = 8 warps (2M x 4N), 64x32 warp tiles.
// SW128-swizzled smem, 3-stage cp.async pipeline, one barrier per slab.
// acc is descaled by dsc in the epilogue.
// mode 0: split: tile n0 < NDI -> o0 (Xp), else o1 (Z)      [bf16]
// mode 1: o0[m,n] = bf16( silu(acc*dsc + bias[n]) )         [bf16]
// mode 2: of[m,n] = acc*dsc + resid[m,n]                    [fp32]
// mode 3: sb = silu(acc*dsc + bias[n]); y = (fm*Sf + bm*sb + Xp*diag)
//         * silu(Z) * gs;  store y*SY -> o8 (Y fp8)
// ---------------------------------------------------------------------------
#define GEMM_SMEM (1024 + 3 * 32768)

__global__ __launch_bounds__(256, 2)
void gemm_mma(const u8* __restrict__ A, const u8* __restrict__ W,
              int K, int mode, float dsc,
              __nv_bfloat16* __restrict__ o0, __nv_bfloat16* __restrict__ o1,
              u8* __restrict__ o8,
              const float* __restrict__ bias, const float* __restrict__ resid,
              float* __restrict__ of, int Nout,
              const __nv_bfloat16* __restrict__ eSf, const __nv_bfloat16* __restrict__ eXp,
              const __nv_bfloat16* __restrict__ eZ,
              const float* __restrict__ diag, const float* __restrict__ gsp)
{
    extern __shared__ char dsm[];
    const u32 dyn  = smem_u32(dsm);
    const u32 base = (dyn + 1023u) & ~1023u;

    const int tid  = threadIdx.x;
    const int wid  = tid >> 5;
    const int lane = tid & 31;
    const int m0   = blockIdx.y << 7;
    const int n0   = blockIdx.x << 7;
    const int warp_m = wid >> 2;      // 0..1
    const int warp_n = wid & 3;       // 0..3

    // ---- cp.async: 4 chunks of 16B per thread per tile (A and B each) ----
    int swoff[4];
    const u8* gA[4];
    const u8* gB[4];
#pragma unroll
    for (int i = 0; i < 4; ++i) {
        const int idx = i * 256 + tid;
        const int row = idx >> 3;       // 0..127
        const int ch  = idx & 7;        // 16B units within 128B row
        swoff[i] = row * 128 + ((ch * 16) ^ ((row & 7) << 4));
        gA[i] = A + (size_t)(m0 + row) * K + ch * 16;
        gB[i] = W + (size_t)(n0 + row) * K + ch * 16;
    }

    // ---- ldmatrix per-lane address components (b16 view; fp8-pair exact) ----
    const int blk = lane >> 3;        // 0..3
    const int lr  = lane & 7;
    int aRow[4], aXr[4];
#pragma unroll
    for (int mi = 0; mi < 4; ++mi) {
        const int r = warp_m * 64 + mi * 16 + (blk & 1) * 8 + lr;
        aRow[mi] = r * 128;
        aXr[mi]  = (r & 7) << 4;
    }
    const int koA = (blk >> 1) * 16;
    int bRow[2], bXr[2];
#pragma unroll
    for (int np = 0; np < 2; ++np) {
        const int r = warp_n * 32 + np * 16 + (blk >> 1) * 8 + lr;
        bRow[np] = r * 128;
        bXr[np]  = (r & 7) << 4;
    }
    const int koB = (blk & 1) * 16;

    float acc[4][4][4];
#pragma unroll
    for (int mi = 0; mi < 4; ++mi)
#pragma unroll
        for (int ni = 0; ni < 4; ++ni)
#pragma unroll
            for (int j = 0; j < 4; ++j) acc[mi][ni][j] = 0.0f;

    const int S = K >> 7;   // 128 fp8 per slab

    // ---- prologue: issue slabs 0 and 1 ----
#pragma unroll
    for (int i = 0; i < 4; ++i) {
        cpa16(base + swoff[i], gA[i]);
        cpa16(base + 16384u + swoff[i], gB[i]);
    }
    CP_COMMIT();
    if (S > 1) {
#pragma unroll
        for (int i = 0; i < 4; ++i) {
            cpa16(base + 32768u + swoff[i], gA[i] + 128);
            cpa16(base + 49152u + swoff[i], gB[i] + 128);
        }
    }
    CP_COMMIT();

    u32 ar = base;                 // read stage
    u32 aw = base + 2u * 32768u;   // write stage (stage 2 first)
    const u32 top = base + 3u * 32768u;

    for (int s = 0; s < S; ++s) {
        if (s < S - 1) { CP_WAIT(1); } else { CP_WAIT(0); }
        __syncthreads();

        if (s + 2 < S) {
            const int k0 = (s + 2) << 7;
#pragma unroll
            for (int i = 0; i < 4; ++i) {
                cpa16(aw + swoff[i], gA[i] + k0);
                cpa16(aw + 16384u + swoff[i], gB[i] + k0);
            }
            aw += 32768u; if (aw == top) aw = base;
        }
        CP_COMMIT();

        const u32 sa = ar;
        const u32 sb = ar + 16384u;
#pragma unroll
        for (int kk = 0; kk < 4; ++kk) {   // 4 x 32B = 128 fp8 k
            u32 a[4][4];
#pragma unroll
            for (int mi = 0; mi < 4; ++mi) {
                const u32 ad = sa + aRow[mi] + ((kk * 32 + koA) ^ aXr[mi]);
                LDSM4(a[mi][0], a[mi][1], a[mi][2], a[mi][3], ad);
            }
            u32 b[4][2];
#pragma unroll
            for (int np = 0; np < 2; ++np) {
                const u32 bd = sb + bRow[np] + ((kk * 32 + koB) ^ bXr[np]);
                LDSM4(b[2*np][0], b[2*np][1], b[2*np+1][0], b[2*np+1][1], bd);
            }
#pragma unroll
            for (int mi = 0; mi < 4; ++mi)
#pragma unroll
                for (int ni = 0; ni < 4; ++ni)
                    MMAFP8(acc[mi][ni], a[mi], b[ni]);
        }
        ar += 32768u; if (ar == top) ar = base;
    }

    // ---- epilogue ----
    const int mrow0 = m0 + warp_m * 64 + (lane >> 2);
    const int ncol0 = n0 + warp_n * 32 + (lane & 3) * 2;

    if (mode == 2) {
#pragma unroll
        for (int mi = 0; mi < 4; ++mi) {
#pragma unroll
            for (int ni = 0; ni < 4; ++ni) {
                const int m = mrow0 + mi * 16;
                const int n = ncol0 + ni * 8;
                const float* c = acc[mi][ni];
                float2 r0 = *(const float2*)(resid + (size_t)m * Nout + n);
                float2 r1 = *(const float2*)(resid + (size_t)(m + 8) * Nout + n);
                float2 v0 = { fmaf(c[0], dsc, r0.x), fmaf(c[1], dsc, r0.y) };
                float2 v1 = { fmaf(c[2], dsc, r1.x), fmaf(c[3], dsc, r1.y) };
                *(float2*)(of + (size_t)m * Nout + n)       = v0;
                *(float2*)(of + (size_t)(m + 8) * Nout + n) = v1;
            }
        }
    } else if (mode == 3) {
        const float gs = gsp[0];
#pragma unroll
        for (int mi = 0; mi < 4; ++mi) {
            const int m  = mrow0 + mi * 16;
            const int t0 = m & (NT - 1);
            const int t1 = (m + 8) & (NT - 1);
            const float fm0 = (t0 > 0) ? 1.0f : 0.0f;
            const float bm0 = (t0 < NT - 1) ? 1.0f : 0.0f;
            const float fm1 = (t1 > 0) ? 1.0f : 0.0f;
            const float bm1 = (t1 < NT - 1) ? 1.0f : 0.0f;
#pragma unroll
            for (int ni = 0; ni < 4; ++ni) {
                const int n = ncol0 + ni * 8;
                const size_t o0i = (size_t)m * NDI + n;
                const size_t o1i = (size_t)(m + 8) * NDI + n;
                const float2 dg = *(const float2*)(diag + n);
                const float b0 = bias[n], b1 = bias[n + 1];

                __nv_bfloat162 sf0 = *(const __nv_bfloat162*)(eSf + o0i);
                __nv_bfloat162 sf1 = *(const __nv_bfloat162*)(eSf + o1i);
                __nv_bfloat162 xp0 = *(const __nv_bfloat162*)(eXp + o0i);
                __nv_bfloat162 xp1 = *(const __nv_bfloat162*)(eXp + o1i);
                __nv_bfloat162 z0  = *(const __nv_bfloat162*)(eZ  + o0i);
                __nv_bfloat162 z1  = *(const __nv_bfloat162*)(eZ  + o1i);

                const float sb00 = silu_f(fmaf(acc[mi][ni][0], dsc, b0));
                const float sb01 = silu_f(fmaf(acc[mi][ni][1], dsc, b1));
                const float sb10 = silu_f(fmaf(acc[mi][ni][2], dsc, b0));
                const float sb11 = silu_f(fmaf(acc[mi][ni][3], dsc, b1));

                float y00 = (fm0 * __bfloat162float(sf0.x) + bm0 * sb00 +
                             __bfloat162float(xp0.x) * dg.x) * silu_f(__bfloat162float(z0.x)) * gs;
                float y01 = (fm0 * __bfloat162float(sf0.y) + bm0 * sb01 +
                             __bfloat162float(xp0.y) * dg.y) * silu_f(__bfloat162float(z0.y)) * gs;
                float y10 = (fm1 * __bfloat162float(sf1.x) + bm1 * sb10 +
                             __bfloat162float(xp1.x) * dg.x) * silu_f(__bfloat162float(z1.x)) * gs;
                float y11 = (fm1 * __bfloat162float(sf1.y) + bm1 * sb11 +
                             __bfloat162float(xp1.y) * dg.y) * silu_f(__bfloat162float(z1.y)) * gs;

                *(u16*)(o8 + o0i) = pack_e4m3_2(y00 * SY, y01 * SY);
                *(u16*)(o8 + o1i) = pack_e4m3_2(y10 * SY, y11 * SY);
            }
        }
    } else {
        __nv_bfloat16* dst = o0;
        int nsub = 0;
        if (mode == 0 && n0 >= NDI) { dst = o1; nsub = NDI; }
#pragma unroll
        for (int mi = 0; mi < 4; ++mi) {
#pragma unroll
            for (int ni = 0; ni < 4; ++ni) {
                const int m = mrow0 + mi * 16;
                const int n = ncol0 + ni * 8;
                float c0 = acc[mi][ni][0] * dsc, c1 = acc[mi][ni][1] * dsc;
                float c2 = acc[mi][ni][2] * dsc, c3 = acc[mi][ni][3] * dsc;
                if (mode == 1) {
                    const float b0 = bias[n], b1 = bias[n + 1];
                    c0 = silu_f(c0 + b0); c1 = silu_f(c1 + b1);
                    c2 = silu_f(c2 + b0); c3 = silu_f(c3 + b1);
                }
                __nv_bfloat162 h0, h1;
                h0.x = __float2bfloat16(c0); h0.y = __float2bfloat16(c1);
                h1.x = __float2bfloat16(c2); h1.y = __float2bfloat16(c3);
                const int nl = n - nsub;
                *(u32*)(dst + (size_t)m * NDI + nl)       = *(u32*)&h0;
                *(u32*)(dst + (size_t)(m + 8) * NDI + nl) = *(u32*)&h1;
            }
        }
    }
}

// ---------------------------------------------------------------------------
// fp32 -> e4m3 convert with scale (8 elements per thread)
// ---------------------------------------------------------------------------
__global__ void cvt8_kernel(const float* __restrict__ src, u8* __restrict__ dst,
                            float scale, int n8)
{
    int i = blockIdx.x * blockDim.x + threadIdx.x;
    if (i >= n8) return;
    const float4 v0 = ((const float4*)src)[i * 2];
    const float4 v1 = ((const float4*)src)[i * 2 + 1];
    uint2 o;
    o.x = pack_e4m3_4(v0.x * scale, v0.y * scale, v0.z * scale, v0.w * scale);
    o.y = pack_e4m3_4(v1.x * scale, v1.y * scale, v1.z * scale, v1.w * scale);
    ((uint2*)dst)[i] = o;
}

// Conv weight transpose: [c][7] fp32 -> [tap][c] fp32 * SA
__global__ void convw_prep(const float* __restrict__ wf, const float* __restrict__ wb)
{
    int i = blockIdx.x * blockDim.x + threadIdx.x;
    if (i >= 7 * NDI) return;
    const int j = i / NDI, c = i - j * NDI;
    g_cwf[i] = wf[c * 7 + j] * SA;
    g_cwb[i] = wb[c * 7 + j] * SA;
}

// ---------------------------------------------------------------------------
// Depthwise causal (fwd) + anti-causal (bwd) conv, smem-tiled, fp8 output.
// Tile: 128 t-rows x 64 channels; strip of 142 rows loaded once.
// ---------------------------------------------------------------------------
#define CT_M 128
#define CT_C 64

__device__ __forceinline__ void unpack8s(uint4 v, float* f) {
    __nv_bfloat162 h;
    h = *(__nv_bfloat162*)&v.x; f[0] = __bfloat162float(h.x); f[1] = __bfloat162float(h.y);
    h = *(__nv_bfloat162*)&v.y; f[2] = __bfloat162float(h.x); f[3] = __bfloat162float(h.y);
    h = *(__nv_bfloat162*)&v.z; f[4] = __bfloat162float(h.x); f[5] = __bfloat162float(h.y);
    h = *(__nv_bfloat162*)&v.w; f[6] = __bfloat162float(h.x); f[7] = __bfloat162float(h.y);
}

__global__ __launch_bounds__(256)
void conv_kernel(const float* __restrict__ bfc, const float* __restrict__ bbc)
{
    __shared__ __nv_bfloat16 sx[142][CT_C];
    __shared__ float swf[7][CT_C], swb[7][CT_C];
    __shared__ float sbf[CT_C], sbb[CT_C];

    const int c0  = blockIdx.x * CT_C;
    const int m0  = blockIdx.y * CT_M;
    const int lo  = m0 & ~(NT - 1);        // batch start row
    const int hi  = lo + NT;
    const int tid = threadIdx.x;

    // weights -> smem (fp32, pre-scaled by SA)
    if (tid < 7 * CT_C / 8) {              // 56 threads, 8 ch each
        const int j = tid >> 3, cc = (tid & 7) * 8;
        *(float4*)&swf[j][cc]     = *(const float4*)(g_cwf + j * NDI + c0 + cc);
        *(float4*)&swf[j][cc + 4] = *(const float4*)(g_cwf + j * NDI + c0 + cc + 4);
        *(float4*)&swb[j][cc]     = *(const float4*)(g_cwb + j * NDI + c0 + cc);
        *(float4*)&swb[j][cc + 4] = *(const float4*)(g_cwb + j * NDI + c0 + cc + 4);
    }
    if (tid >= 64 && tid < 64 + CT_C / 4) {
        const int q = (tid - 64) * 4;
        const float4 f0 = *(const float4*)(bfc + c0 + q);
        const float4 f1 = *(const float4*)(bbc + c0 + q);
        sbf[q] = f0.x * SA; sbf[q+1] = f0.y * SA; sbf[q+2] = f0.z * SA; sbf[q+3] = f0.w * SA;
        sbb[q] = f1.x * SA; sbb[q+1] = f1.y * SA; sbb[q+2] = f1.z * SA; sbb[q+3] = f1.w * SA;
    }

    // Xp strip: rows m0-7 .. m0+134, zero outside batch
    for (int u = tid; u < 142 * 8; u += 256) {
        const int r = u >> 3, cc = (u & 7) * 8;
        const int m = m0 - 7 + r;
        uint4 v = make_uint4(0, 0, 0, 0);
        if (m >= lo && m < hi)
            v = *(const uint4*)(g_Xp + (size_t)m * NDI + c0 + cc);
        *(uint4*)&sx[r][cc] = v;
    }
    __syncthreads();

    // compute: 128 rows x 8 units of 8 channels
    for (int u = tid; u < CT_M * 8; u += 256) {
        const int r  = u >> 3, cc = (u & 7) * 8;
        const int m  = m0 + r;
        float accf[8], accb[8];
#pragma unroll
        for (int q = 0; q < 8; ++q) { accf[q] = sbf[cc + q]; accb[q] = sbb[cc + q]; }
#pragma unroll
        for (int k = 0; k < 7; ++k) {
            float xf[8], xb[8];
            unpack8s(*(const uint4*)&sx[r + k][cc], xf);          // Xp[m-7+k]
            unpack8s(*(const uint4*)&sx[r + 14 - k][cc], xb);     // Xp[m+7-k]
#pragma unroll
            for (int q = 0; q < 8; ++q) {
                accf[q] = fmaf(swf[k][cc + q], xf[q], accf[q]);
                accb[q] = fmaf(swb[k][cc + q], xb[q], accb[q]);
            }
        }
        const size_t o = (size_t)m * NDI + c0 + cc;
        uint2 pf, pb;
        pf.x = pack_e4m3_4(accf[0], accf[1], accf[2], accf[3]);
        pf.y = pack_e4m3_4(accf[4], accf[5], accf[6], accf[7]);
        pb.x = pack_e4m3_4(accb[0], accb[1], accb[2], accb[3]);
        pb.y = pack_e4m3_4(accb[4], accb[5], accb[6], accb[7]);
        *(uint2*)(g_Af8 + o) = pf;
        *(uint2*)(g_Ab8 + o) = pb;
    }
}

// ---------------------------------------------------------------------------
// LayerNorm over last dim (512), one block (128 threads) per row.
// ---------------------------------------------------------------------------
__global__ void ln_kernel(const float* __restrict__ lng, const float* __restrict__ lnb,
                          float* __restrict__ out)
{
    const int row = blockIdx.x;
    const int tid = threadIdx.x;                 // 0..127

    const float4 v = ((const float4*)(g_H + (size_t)row * ND))[tid];
    float s  = v.x + v.y + v.z + v.w;
    float ss = v.x*v.x + v.y*v.y + v.z*v.z + v.w*v.w;

#pragma unroll
    for (int o = 16; o > 0; o >>= 1) {
        s  += __shfl_xor_sync(0xffffffffu, s,  o);
        ss += __shfl_xor_sync(0xffffffffu, ss, o);
    }
    __shared__ float shs[4], shss[4];
    if ((tid & 31) == 0) { shs[tid >> 5] = s; shss[tid >> 5] = ss; }
    __syncthreads();
    s  = shs[0]  + shs[1]  + shs[2]  + shs[3];
    ss = shss[0] + shss[1] + shss[2] + shss[3];

    const float mu  = s * (1.0f / ND);
    const float var = ss * (1.0f / ND) - mu * mu;
    const float inv = rsqrtf(var + 1e-5f);

    const float4 g4 = ((const float4*)lng)[tid];
    const float4 b4 = ((const float4*)lnb)[tid];
    float4 o4;
    o4.x = (v.x - mu) * inv * g4.x + b4.x;
    o4.y = (v.y - mu) * inv * g4.y + b4.y;
    o4.z = (v.z - mu) * inv * g4.z + b4.z;
    o4.w = (v.w - mu) * inv * g4.w + b4.w;
    ((float4*)(out + (size_t)row * ND))[tid] = o4;
}

// ---------------------------------------------------------------------------
// Launch
// ---------------------------------------------------------------------------
extern "C" void kernel_launch(void* const* d_in, const int* in_sizes, int n_in,
                              void* d_out, int out_size)
{
    const float* x    = (const float*)d_in[0];   // (B,T,D)
    const float* winp = (const float*)d_in[1];   // (2*DI, D)
    const float* wcf  = (const float*)d_in[2];   // (DI,1,K)
    const float* bcf  = (const float*)d_in[3];   // (DI,)
    const float* wpf  = (const float*)d_in[4];   // (DI,DI)
    const float* bpf  = (const float*)d_in[5];   // (DI,)
    const float* wcb  = (const float*)d_in[6];
    const float* bcb  = (const float*)d_in[7];
    const float* wpb  = (const float*)d_in[8];
    const float* bpb  = (const float*)d_in[9];
    const float* diag = (const float*)d_in[10];  // (DI,)
    const float* gsc  = (const float*)d_in[11];  // (1,)
    const float* wout = (const float*)d_in[12];  // (D, DI)
    const float* lng  = (const float*)d_in[13];  // (D,)
    const float* lnb  = (const float*)d_in[14];  // (D,)
    float* out = (float*)d_out;

    u8 *px8, *pwi8, *pwpf8, *pwpb8, *pwo8, *pAf8, *pAb8, *pY8;
    __nv_bfloat16 *pXp, *pZ, *pSf;
    float *pH;
    cudaGetSymbolAddress((void**)&px8,  g_x8);
    cudaGetSymbolAddress((void**)&pwi8, g_wi8);
    cudaGetSymbolAddress((void**)&pwpf8, g_wpf8);
    cudaGetSymbolAddress((void**)&pwpb8, g_wpb8);
    cudaGetSymbolAddress((void**)&pwo8, g_wo8);
    cudaGetSymbolAddress((void**)&pAf8, g_Af8);
    cudaGetSymbolAddress((void**)&pAb8, g_Ab8);
    cudaGetSymbolAddress((void**)&pY8,  g_Y8);
    cudaGetSymbolAddress((void**)&pXp,  g_Xp);
    cudaGetSymbolAddress((void**)&pZ,   g_Z);
    cudaGetSymbolAddress((void**)&pSf,  g_Sf);
    cudaGetSymbolAddress((void**)&pH,   g_H);

    cudaFuncSetAttribute(gemm_mma, cudaFuncAttributeMaxDynamicSharedMemorySize, GEMM_SMEM);

    // 0) fp32 -> fp8 conversions (scaled) + conv weight prep
    cvt8_kernel<<<(NM * ND / 8 + 255) / 256, 256>>>(x,    px8,  SX, NM * ND / 8);
    cvt8_kernel<<<(2 * NDI * ND / 8 + 255) / 256, 256>>>(winp, pwi8, SW, 2 * NDI * ND / 8);
    cvt8_kernel<<<(NDI * NDI / 8 + 255) / 256, 256>>>(wpf,  pwpf8, SW, NDI * NDI / 8);
    cvt8_kernel<<<(NDI * NDI / 8 + 255) / 256, 256>>>(wpb,  pwpb8, SW, NDI * NDI / 8);
    cvt8_kernel<<<(ND * NDI / 8 + 255) / 256, 256>>>(wout, pwo8, SW, ND * NDI / 8);
    convw_prep<<<(7 * NDI + 255) / 256, 256>>>(wcf, wcb);

    // 1) in_proj: split into Xp, Z (bf16);  dsc = 1/(SX*SW)
    gemm_mma<<<dim3(2 * NDI / 128, NM / 128), 256, GEMM_SMEM>>>(
        px8, pwi8, ND, 0, 1.0f / (SX * SW), pXp, pZ, nullptr,
        nullptr, nullptr, nullptr, 2 * NDI,
        nullptr, nullptr, nullptr, nullptr, nullptr);

    // 2) depthwise convs -> Af8, Ab8 (fp8 * SA)
    conv_kernel<<<dim3(NDI / CT_C, NM / CT_M), 256>>>(bcf, bcb);

    // 3) fwd proj, fused bias+silu -> Sf (bf16);  dsc = 1/(SA*SW)
    gemm_mma<<<dim3(NDI / 128, NM / 128), 256, GEMM_SMEM>>>(
        pAf8, pwpf8, NDI, 1, 1.0f / (SA * SW), pSf, nullptr, nullptr,
        bpf, nullptr, nullptr, NDI,
        nullptr, nullptr, nullptr, nullptr, nullptr);

    // 4) bwd proj, fused bias+silu+combine+gate -> Y8 (fp8 * SY)
    gemm_mma<<<dim3(NDI / 128, NM / 128), 256, GEMM_SMEM>>>(
        pAb8, pwpb8, NDI, 3, 1.0f / (SA * SW), nullptr, nullptr, pY8,
        bpb, nullptr, nullptr, NDI,
        pSf, pXp, pZ, diag, gsc);

    // 5) out_proj + residual -> H (fp32);  dsc = 1/(SY*SW)
    gemm_mma<<<dim3(ND / 128, NM / 128), 256, GEMM_SMEM>>>(
        pY8, pwo8, NDI, 2, 1.0f / (SY * SW), nullptr, nullptr, nullptr,
        nullptr, x, pH, ND,
        nullptr, nullptr, nullptr, nullptr, nullptr);

    // 6) LayerNorm -> out
    ln_kernel<<<NM, 128>>>(lng, lnb, out);
}

// round 12
// speedup vs baseline: 1.1210x; 1.1210x over previous
#include <cuda_runtime.h>
#include <cuda_fp16.h>

typedef unsigned int u32;

// Problem constants
#define NB   8
#define NT   4096
#define ND   512
#define NDI  1024
#define NM   (NB * NT)   // 32768 rows (B*T)

// ---------------------------------------------------------------------------
// Scratch (static __device__ arrays; no allocations allowed)
// ---------------------------------------------------------------------------
__device__ __half g_xh [NM * ND];        // x fp16 (GEMM1 A)
__device__ __half g_wi [2 * NDI * ND];   // in_proj_w fp16
__device__ __half g_wpf[NDI * NDI];      // proj_fwd_w fp16
__device__ __half g_wpb[NDI * NDI];      // proj_bwd_w fp16
__device__ __half g_wo [ND * NDI];       // out_proj_w fp16
__device__ float  g_cwf[7 * NDI];        // conv fwd w, [tap][chan] fp32
__device__ float  g_cwb[7 * NDI];        // conv bwd w, [tap][chan] fp32
__device__ __half g_Xp[NM * NDI];        // x_proj fp16
__device__ __half g_Z [NM * NDI];        // z fp16
__device__ __half g_Af[NM * NDI];        // conv fwd out fp16
__device__ __half g_Ab[NM * NDI];        // conv bwd out fp16
__device__ __half g_Sf[NM * NDI];        // silu(proj_fwd + bias) fp16
__device__ __half g_Y [NM * NDI];        // gated mixer output fp16
__device__ float  g_H [NM * ND];         // residual + out_proj (fp32)

__device__ __forceinline__ float silu_f(float x) {
    return x / (1.0f + __expf(-x));
}

__device__ __forceinline__ u32 smem_u32(const void* p) {
    u32 a;
    asm("{ .reg .u64 t; cvta.to.shared.u64 t, %1; cvt.u32.u64 %0, t; }"
        : "=r"(a) : "l"(p));
    return a;
}

// ---------------------------------------------------------------------------
// PTX primitives: cp.async, ldmatrix, mma (all compute_103-base legal)
// ---------------------------------------------------------------------------
__device__ __forceinline__ void cpa16(u32 s, const void* g) {
    asm volatile("cp.async.cg.shared.global [%0], [%1], 16;" :: "r"(s), "l"(g));
}
#define CP_COMMIT()  asm volatile("cp.async.commit_group;" ::: "memory")
#define CP_WAIT(N)   asm volatile("cp.async.wait_group %0;" :: "n"(N) : "memory")

#define LDSM4(r0, r1, r2, r3, addr) \
    asm volatile("ldmatrix.sync.aligned.m8n8.x4.shared.b16 {%0,%1,%2,%3}, [%4];" \
        : "=r"(r0), "=r"(r1), "=r"(r2), "=r"(r3) : "r"(addr))

// f16 x f16 -> f16 accumulate (tests double-rate HMMA on sm_103 legacy path)
#define MMA16816H(c, a, b) \
    asm volatile("mma.sync.aligned.m16n8k16.row.col.f16.f16.f16.f16 " \
        "{%0,%1}, {%2,%3,%4,%5}, {%6,%7}, {%0,%1};" \
        : "+r"((c)[0]), "+r"((c)[1]) \
        : "r"((a)[0]), "r"((a)[1]), "r"((a)[2]), "r"((a)[3]), \
          "r"((b)[0]), "r"((b)[1]))

// ---------------------------------------------------------------------------
// Warp-MMA GEMM: C[m,n] = sum_k A[m,k]*W[n,k], fp16 in, fp16 accum.
// BM=BN=128, BK=64, 256 threads = 8 warps (2M x 4N), 64x32 warp tiles.
// SW128-swizzled smem, 3-stage cp.async pipeline, one barrier per slab.
// mode 0: split: tile n0 < NDI -> o0 (Xp), else o1 (Z)    [fp16]
// mode 1: o0[m,n] = h( silu(acc + bias[n]) )              [fp16]
// mode 2: of[m,n] = acc + resid[m,n]                      [fp32]
// mode 3: sb = silu(acc + bias[n]);  (combine fused)
//         y = (fm*Sf + bm*sb + Xp*diag) * silu(Z) * gs -> o0 (Y) [fp16]
// ---------------------------------------------------------------------------
#define GEMM_SMEM (1024 + 3 * 32768)

__global__ __launch_bounds__(256, 2)
void gemm_mma(const __half* __restrict__ A, const __half* __restrict__ W,
              int K, int mode,
              __half* __restrict__ o0, __half* __restrict__ o1,
              const float* __restrict__ bias, const float* __restrict__ resid,
              float* __restrict__ of, int Nout,
              const __half* __restrict__ eSf, const __half* __restrict__ eXp,
              const __half* __restrict__ eZ,
              const float* __restrict__ diag, const float* __restrict__ gsp)
{
    extern __shared__ char dsm[];
    const u32 dyn  = smem_u32(dsm);
    const u32 base = (dyn + 1023u) & ~1023u;

    const int tid  = threadIdx.x;
    const int wid  = tid >> 5;
    const int lane = tid & 31;
    const int m0   = blockIdx.y << 7;
    const int n0   = blockIdx.x << 7;
    const int warp_m = wid >> 2;      // 0..1
    const int warp_n = wid & 3;       // 0..3

    // ---- cp.async assignments: 4 chunks of 16B per thread per tile ----
    int swoff[4];
    const __half* gA[4];
    const __half* gB[4];
#pragma unroll
    for (int i = 0; i < 4; ++i) {
        const int idx = i * 256 + tid;
        const int row = idx >> 3;
        const int ch  = idx & 7;
        swoff[i] = row * 128 + ((ch * 16) ^ ((row & 7) << 4));
        gA[i] = A + (size_t)(m0 + row) * K + ch * 8;
        gB[i] = W + (size_t)(n0 + row) * K + ch * 8;
    }

    // ---- ldmatrix per-lane address components ----
    const int blk = lane >> 3;        // 0..3
    const int lr  = lane & 7;
    int aRow[4], aXr[4];
#pragma unroll
    for (int mi = 0; mi < 4; ++mi) {
        const int r = warp_m * 64 + mi * 16 + (blk & 1) * 8 + lr;
        aRow[mi] = r * 128;
        aXr[mi]  = (r & 7) << 4;
    }
    const int koA = (blk >> 1) * 16;
    int bRow[2], bXr[2];
#pragma unroll
    for (int np = 0; np < 2; ++np) {
        const int r = warp_n * 32 + np * 16 + (blk >> 1) * 8 + lr;
        bRow[np] = r * 128;
        bXr[np]  = (r & 7) << 4;
    }
    const int koB = (blk & 1) * 16;

    // f16x2 accumulators: [mi][ni][2 regs of 2 halves]
    u32 acc[4][4][2];
#pragma unroll
    for (int mi = 0; mi < 4; ++mi)
#pragma unroll
        for (int ni = 0; ni < 4; ++ni) { acc[mi][ni][0] = 0u; acc[mi][ni][1] = 0u; }

    const int S = K >> 6;

    // ---- prologue: issue slabs 0 and 1 ----
#pragma unroll
    for (int i = 0; i < 4; ++i) {
        cpa16(base + swoff[i], gA[i]);
        cpa16(base + 16384u + swoff[i], gB[i]);
    }
    CP_COMMIT();
    if (S > 1) {
#pragma unroll
        for (int i = 0; i < 4; ++i) {
            cpa16(base + 32768u + swoff[i], gA[i] + 64);
            cpa16(base + 49152u + swoff[i], gB[i] + 64);
        }
    }
    CP_COMMIT();

    u32 ar = base;                 // read stage
    u32 aw = base + 2u * 32768u;   // write stage (stage 2 first)
    const u32 top = base + 3u * 32768u;

    for (int s = 0; s < S; ++s) {
        if (s < S - 1) { CP_WAIT(1); } else { CP_WAIT(0); }
        __syncthreads();

        if (s + 2 < S) {
            const int k0 = (s + 2) << 6;
#pragma unroll
            for (int i = 0; i < 4; ++i) {
                cpa16(aw + swoff[i], gA[i] + k0);
                cpa16(aw + 16384u + swoff[i], gB[i] + k0);
            }
            aw += 32768u; if (aw == top) aw = base;
        }
        CP_COMMIT();

        const u32 sa = ar;
        const u32 sb = ar + 16384u;
#pragma unroll
        for (int kk = 0; kk < 4; ++kk) {
            u32 a[4][4];
#pragma unroll
            for (int mi = 0; mi < 4; ++mi) {
                const u32 ad = sa + aRow[mi] + ((kk * 32 + koA) ^ aXr[mi]);
                LDSM4(a[mi][0], a[mi][1], a[mi][2], a[mi][3], ad);
            }
            u32 b[4][2];
#pragma unroll
            for (int np = 0; np < 2; ++np) {
                const u32 bd = sb + bRow[np] + ((kk * 32 + koB) ^ bXr[np]);
                LDSM4(b[2*np][0], b[2*np][1], b[2*np+1][0], b[2*np+1][1], bd);
            }
#pragma unroll
            for (int mi = 0; mi < 4; ++mi)
#pragma unroll
                for (int ni = 0; ni < 4; ++ni)
                    MMA16816H(acc[mi][ni], a[mi], b[ni]);
        }
        ar += 32768u; if (ar == top) ar = base;
    }

    // ---- epilogue ----
    const int mrow0 = m0 + warp_m * 64 + (lane >> 2);
    const int ncol0 = n0 + warp_n * 32 + (lane & 3) * 2;

    if (mode == 2) {
#pragma unroll
        for (int mi = 0; mi < 4; ++mi) {
#pragma unroll
            for (int ni = 0; ni < 4; ++ni) {
                const int m = mrow0 + mi * 16;
                const int n = ncol0 + ni * 8;
                const float2 c01 = __half22float2(*(__half2*)&acc[mi][ni][0]);
                const float2 c23 = __half22float2(*(__half2*)&acc[mi][ni][1]);
                float2 r0 = *(const float2*)(resid + (size_t)m * Nout + n);
                float2 r1 = *(const float2*)(resid + (size_t)(m + 8) * Nout + n);
                float2 v0 = { c01.x + r0.x, c01.y + r0.y };
                float2 v1 = { c23.x + r1.x, c23.y + r1.y };
                *(float2*)(of + (size_t)m * Nout + n)       = v0;
                *(float2*)(of + (size_t)(m + 8) * Nout + n) = v1;
            }
        }
    } else if (mode == 3) {
        const float gs = gsp[0];
#pragma unroll
        for (int mi = 0; mi < 4; ++mi) {
            const int m  = mrow0 + mi * 16;
            const int t0 = m & (NT - 1);
            const int t1 = (m + 8) & (NT - 1);
            const float fm0 = (t0 > 0) ? 1.0f : 0.0f;
            const float bm0 = (t0 < NT - 1) ? 1.0f : 0.0f;
            const float fm1 = (t1 > 0) ? 1.0f : 0.0f;
            const float bm1 = (t1 < NT - 1) ? 1.0f : 0.0f;
#pragma unroll
            for (int ni = 0; ni < 4; ++ni) {
                const int n = ncol0 + ni * 8;
                const size_t o0i = (size_t)m * NDI + n;
                const size_t o1i = (size_t)(m + 8) * NDI + n;
                const float2 dg = *(const float2*)(diag + n);
                const float b0 = bias[n], b1 = bias[n + 1];

                const float2 c01 = __half22float2(*(__half2*)&acc[mi][ni][0]);
                const float2 c23 = __half22float2(*(__half2*)&acc[mi][ni][1]);

                float2 sf0 = __half22float2(*(const __half2*)(eSf + o0i));
                float2 sf1 = __half22float2(*(const __half2*)(eSf + o1i));
                float2 xp0 = __half22float2(*(const __half2*)(eXp + o0i));
                float2 xp1 = __half22float2(*(const __half2*)(eXp + o1i));
                float2 z0  = __half22float2(*(const __half2*)(eZ  + o0i));
                float2 z1  = __half22float2(*(const __half2*)(eZ  + o1i));

                const float sb00 = silu_f(c01.x + b0);
                const float sb01 = silu_f(c01.y + b1);
                const float sb10 = silu_f(c23.x + b0);
                const float sb11 = silu_f(c23.y + b1);

                float y00 = (fm0 * sf0.x + bm0 * sb00 + xp0.x * dg.x) * silu_f(z0.x) * gs;
                float y01 = (fm0 * sf0.y + bm0 * sb01 + xp0.y * dg.y) * silu_f(z0.y) * gs;
                float y10 = (fm1 * sf1.x + bm1 * sb10 + xp1.x * dg.x) * silu_f(z1.x) * gs;
                float y11 = (fm1 * sf1.y + bm1 * sb11 + xp1.y * dg.y) * silu_f(z1.y) * gs;

                *(__half2*)(o0 + o0i) = __floats2half2_rn(y00, y01);
                *(__half2*)(o0 + o1i) = __floats2half2_rn(y10, y11);
            }
        }
    } else {
        __half* dst = o0;
        int nsub = 0;
        if (mode == 0 && n0 >= NDI) { dst = o1; nsub = NDI; }
#pragma unroll
        for (int mi = 0; mi < 4; ++mi) {
#pragma unroll
            for (int ni = 0; ni < 4; ++ni) {
                const int m = mrow0 + mi * 16;
                const int n = ncol0 + ni * 8;
                float2 c01 = __half22float2(*(__half2*)&acc[mi][ni][0]);
                float2 c23 = __half22float2(*(__half2*)&acc[mi][ni][1]);
                if (mode == 1) {
                    const float b0 = bias[n], b1 = bias[n + 1];
                    c01.x = silu_f(c01.x + b0); c01.y = silu_f(c01.y + b1);
                    c23.x = silu_f(c23.x + b0); c23.y = silu_f(c23.y + b1);
                }
                const int nl = n - nsub;
                *(__half2*)(dst + (size_t)m * NDI + nl)       = __floats2half2_rn(c01.x, c01.y);
                *(__half2*)(dst + (size_t)(m + 8) * NDI + nl) = __floats2half2_rn(c23.x, c23.y);
            }
        }
    }
}

// ---------------------------------------------------------------------------
// fp32 -> fp16 convert (vectorized by 4)
// ---------------------------------------------------------------------------
__global__ void cvt_kernel(const float* __restrict__ src, __half* __restrict__ dst, int n4)
{
    int i = blockIdx.x * blockDim.x + threadIdx.x;
    if (i >= n4) return;
    float4 v = ((const float4*)src)[i];
    __half2 h0 = __floats2half2_rn(v.x, v.y);
    __half2 h1 = __floats2half2_rn(v.z, v.w);
    uint2 o;
    o.x = *(u32*)&h0; o.y = *(u32*)&h1;
    ((uint2*)dst)[i] = o;
}

// Conv weight transpose: [c][7] fp32 -> [tap][c] fp32
__global__ void convw_prep(const float* __restrict__ wf, const float* __restrict__ wb)
{
    int i = blockIdx.x * blockDim.x + threadIdx.x;
    if (i >= 7 * NDI) return;
    const int j = i / NDI, c = i - j * NDI;
    g_cwf[i] = wf[c * 7 + j];
    g_cwb[i] = wb[c * 7 + j];
}

// ---------------------------------------------------------------------------
// Depthwise causal (fwd) + anti-causal (bwd) conv, smem-tiled.
// Tile: 128 t-rows x 64 channels; strip of 142 rows loaded once.
// ---------------------------------------------------------------------------
#define CT_M 128
#define CT_C 64

__device__ __forceinline__ void unpack8h(uint4 v, float* f) {
    float2 p;
    p = __half22float2(*(__half2*)&v.x); f[0] = p.x; f[1] = p.y;
    p = __half22float2(*(__half2*)&v.y); f[2] = p.x; f[3] = p.y;
    p = __half22float2(*(__half2*)&v.z); f[4] = p.x; f[5] = p.y;
    p = __half22float2(*(__half2*)&v.w); f[6] = p.x; f[7] = p.y;
}

__device__ __forceinline__ uint4 pack8h(const float* f) {
    u32 pk[4];
#pragma unroll
    for (int j = 0; j < 4; ++j) {
        __half2 h = __floats2half2_rn(f[2*j], f[2*j+1]);
        pk[j] = *(u32*)&h;
    }
    return *(uint4*)pk;
}

__global__ __launch_bounds__(256)
void conv_kernel(const float* __restrict__ bfc, const float* __restrict__ bbc)
{
    __shared__ __half sx[142][CT_C];
    __shared__ float swf[7][CT_C], swb[7][CT_C];
    __shared__ float sbf[CT_C], sbb[CT_C];

    const int c0  = blockIdx.x * CT_C;
    const int m0  = blockIdx.y * CT_M;
    const int lo  = m0 & ~(NT - 1);        // batch start row
    const int hi  = lo + NT;
    const int tid = threadIdx.x;

    // weights -> smem (fp32)
    if (tid < 7 * CT_C / 8) {              // 56 threads, 8 ch each
        const int j = tid >> 3, cc = (tid & 7) * 8;
        *(float4*)&swf[j][cc]     = *(const float4*)(g_cwf + j * NDI + c0 + cc);
        *(float4*)&swf[j][cc + 4] = *(const float4*)(g_cwf + j * NDI + c0 + cc + 4);
        *(float4*)&swb[j][cc]     = *(const float4*)(g_cwb + j * NDI + c0 + cc);
        *(float4*)&swb[j][cc + 4] = *(const float4*)(g_cwb + j * NDI + c0 + cc + 4);
    }
    if (tid >= 64 && tid < 64 + CT_C / 4) {
        const int q = (tid - 64) * 4;
        *(float4*)&sbf[q] = *(const float4*)(bfc + c0 + q);
        *(float4*)&sbb[q] = *(const float4*)(bbc + c0 + q);
    }

    // Xp strip: rows m0-7 .. m0+134, zero outside batch
    for (int u = tid; u < 142 * 8; u += 256) {
        const int r = u >> 3, cc = (u & 7) * 8;
        const int m = m0 - 7 + r;
        uint4 v = make_uint4(0, 0, 0, 0);
        if (m >= lo && m < hi)
            v = *(const uint4*)(g_Xp + (size_t)m * NDI + c0 + cc);
        *(uint4*)&sx[r][cc] = v;
    }
    __syncthreads();

    // compute: 128 rows x 8 units of 8 channels
    for (int u = tid; u < CT_M * 8; u += 256) {
        const int r  = u >> 3, cc = (u & 7) * 8;
        const int m  = m0 + r;
        float accf[8], accb[8];
#pragma unroll
        for (int q = 0; q < 8; ++q) { accf[q] = sbf[cc + q]; accb[q] = sbb[cc + q]; }
#pragma unroll
        for (int k = 0; k < 7; ++k) {
            float xf[8], xb[8];
            unpack8h(*(const uint4*)&sx[r + k][cc], xf);          // Xp[m-7+k]
            unpack8h(*(const uint4*)&sx[r + 14 - k][cc], xb);     // Xp[m+7-k]
#pragma unroll
            for (int q = 0; q < 8; ++q) {
                accf[q] = fmaf(swf[k][cc + q], xf[q], accf[q]);
                accb[q] = fmaf(swb[k][cc + q], xb[q], accb[q]);
            }
        }
        const size_t o = (size_t)m * NDI + c0 + cc;
        *(uint4*)(g_Af + o) = pack8h(accf);
        *(uint4*)(g_Ab + o) = pack8h(accb);
    }
}

// ---------------------------------------------------------------------------
// LayerNorm over last dim (512), one block (128 threads) per row.
// ---------------------------------------------------------------------------
__global__ void ln_kernel(const float* __restrict__ lng, const float* __restrict__ lnb,
                          float* __restrict__ out)
{
    const int row = blockIdx.x;
    const int tid = threadIdx.x;                 // 0..127

    const float4 v = ((const float4*)(g_H + (size_t)row * ND))[tid];
    float s  = v.x + v.y + v.z + v.w;
    float ss = v.x*v.x + v.y*v.y + v.z*v.z + v.w*v.w;

#pragma unroll
    for (int o = 16; o > 0; o >>= 1) {
        s  += __shfl_xor_sync(0xffffffffu, s,  o);
        ss += __shfl_xor_sync(0xffffffffu, ss, o);
    }
    __shared__ float shs[4], shss[4];
    if ((tid & 31) == 0) { shs[tid >> 5] = s; shss[tid >> 5] = ss; }
    __syncthreads();
    s  = shs[0]  + shs[1]  + shs[2]  + shs[3];
    ss = shss[0] + shss[1] + shss[2] + shss[3];

    const float mu  = s * (1.0f / ND);
    const float var = ss * (1.0f / ND) - mu * mu;
    const float inv = rsqrtf(var + 1e-5f);

    const float4 g4 = ((const float4*)lng)[tid];
    const float4 b4 = ((const float4*)lnb)[tid];
    float4 o4;
    o4.x = (v.x - mu) * inv * g4.x + b4.x;
    o4.y = (v.y - mu) * inv * g4.y + b4.y;
    o4.z = (v.z - mu) * inv * g4.z + b4.z;
    o4.w = (v.w - mu) * inv * g4.w + b4.w;
    ((float4*)(out + (size_t)row * ND))[tid] = o4;
}

// ---------------------------------------------------------------------------
// Launch
// ---------------------------------------------------------------------------
extern "C" void kernel_launch(void* const* d_in, const int* in_sizes, int n_in,
                              void* d_out, int out_size)
{
    const float* x    = (const float*)d_in[0];   // (B,T,D)
    const float* winp = (const float*)d_in[1];   // (2*DI, D)
    const float* wcf  = (const float*)d_in[2];   // (DI,1,K)
    const float* bcf  = (const float*)d_in[3];   // (DI,)
    const float* wpf  = (const float*)d_in[4];   // (DI,DI)
    const float* bpf  = (const float*)d_in[5];   // (DI,)
    const float* wcb  = (const float*)d_in[6];
    const float* bcb  = (const float*)d_in[7];
    const float* wpb  = (const float*)d_in[8];
    const float* bpb  = (const float*)d_in[9];
    const float* diag = (const float*)d_in[10];  // (DI,)
    const float* gsc  = (const float*)d_in[11];  // (1,)
    const float* wout = (const float*)d_in[12];  // (D, DI)
    const float* lng  = (const float*)d_in[13];  // (D,)
    const float* lnb  = (const float*)d_in[14];  // (D,)
    float* out = (float*)d_out;

    __half *pxh, *pwi, *pwpf, *pwpb, *pwo;
    __half *pXp, *pZ, *pAf, *pAb, *pSf, *pY;
    float *pH;
    cudaGetSymbolAddress((void**)&pxh,  g_xh);
    cudaGetSymbolAddress((void**)&pwi,  g_wi);
    cudaGetSymbolAddress((void**)&pwpf, g_wpf);
    cudaGetSymbolAddress((void**)&pwpb, g_wpb);
    cudaGetSymbolAddress((void**)&pwo,  g_wo);
    cudaGetSymbolAddress((void**)&pXp,  g_Xp);
    cudaGetSymbolAddress((void**)&pZ,   g_Z);
    cudaGetSymbolAddress((void**)&pAf,  g_Af);
    cudaGetSymbolAddress((void**)&pAb,  g_Ab);
    cudaGetSymbolAddress((void**)&pSf,  g_Sf);
    cudaGetSymbolAddress((void**)&pY,   g_Y);
    cudaGetSymbolAddress((void**)&pH,   g_H);

    cudaFuncSetAttribute(gemm_mma, cudaFuncAttributeMaxDynamicSharedMemorySize, GEMM_SMEM);

    // 0) fp32 -> fp16 conversions + conv weight transpose
    cvt_kernel<<<(NM * ND / 4 + 255) / 256, 256>>>(x,    pxh, NM * ND / 4);
    cvt_kernel<<<(2 * NDI * ND / 4 + 255) / 256, 256>>>(winp, pwi,  2 * NDI * ND / 4);
    cvt_kernel<<<(NDI * NDI / 4 + 255) / 256, 256>>>(wpf,  pwpf, NDI * NDI / 4);
    cvt_kernel<<<(NDI * NDI / 4 + 255) / 256, 256>>>(wpb,  pwpb, NDI * NDI / 4);
    cvt_kernel<<<(ND * NDI / 4 + 255) / 256, 256>>>(wout, pwo,  ND * NDI / 4);
    convw_prep<<<(7 * NDI + 255) / 256, 256>>>(wcf, wcb);

    // 1) in_proj: split into Xp, Z (fp16)
    gemm_mma<<<dim3(2 * NDI / 128, NM / 128), 256, GEMM_SMEM>>>(
        pxh, pwi, ND, 0, pXp, pZ, nullptr, nullptr, nullptr, 2 * NDI,
        nullptr, nullptr, nullptr, nullptr, nullptr);

    // 2) depthwise convs -> Af, Ab (fp16)
    conv_kernel<<<dim3(NDI / CT_C, NM / CT_M), 256>>>(bcf, bcb);

    // 3) fwd proj with fused bias + silu -> Sf (fp16)
    gemm_mma<<<dim3(NDI / 128, NM / 128), 256, GEMM_SMEM>>>(
        pAf, pwpf, NDI, 1, pSf, nullptr, bpf, nullptr, nullptr, NDI,
        nullptr, nullptr, nullptr, nullptr, nullptr);

    // 4) bwd proj with fused bias + silu + combine + gate -> Y (fp16)
    gemm_mma<<<dim3(NDI / 128, NM / 128), 256, GEMM_SMEM>>>(
        pAb, pwpb, NDI, 3, pY, nullptr, bpb, nullptr, nullptr, NDI,
        pSf, pXp, pZ, diag, gsc);

    // 5) out_proj + residual -> H (fp32)
    gemm_mma<<<dim3(ND / 128, NM / 128), 256, GEMM_SMEM>>>(
        pY, pwo, NDI, 2, nullptr, nullptr, nullptr, x, pH, ND,
        nullptr, nullptr, nullptr, nullptr, nullptr);

    // 6) LayerNorm -> out
    ln_kernel<<<NM, 128>>>(lng, lnb, out);
}

// round 13
// speedup vs baseline: 1.1705x; 1.0441x over previous
#include <cuda_runtime.h>
#include <cuda_bf16.h>

typedef unsigned int u32;

// Problem constants
#define NB   8
#define NT   4096
#define ND   512
#define NDI  1024
#define NM   (NB * NT)   // 32768 rows (B*T)

// ---------------------------------------------------------------------------
// Scratch (static __device__ arrays; no allocations allowed)
// ---------------------------------------------------------------------------
__device__ __nv_bfloat16 g_xbf[NM * ND];        // x in bf16 (GEMM1 A)
__device__ __nv_bfloat16 g_wi [2 * NDI * ND];   // in_proj_w bf16
__device__ __nv_bfloat16 g_wpf[NDI * NDI];      // proj_fwd_w bf16
__device__ __nv_bfloat16 g_wpb[NDI * NDI];      // proj_bwd_w bf16
__device__ __nv_bfloat16 g_wo [ND * NDI];       // out_proj_w bf16
__device__ float  g_cwf[7 * NDI];               // conv fwd w, [tap][chan] fp32
__device__ float  g_cwb[7 * NDI];               // conv bwd w, [tap][chan] fp32
__device__ __nv_bfloat16 g_Xp[NM * NDI];        // x_proj bf16
__device__ __nv_bfloat16 g_Z [NM * NDI];        // z bf16
__device__ __nv_bfloat16 g_Af[NM * NDI];        // conv fwd out bf16
__device__ __nv_bfloat16 g_Ab[NM * NDI];        // conv bwd out bf16
__device__ __nv_bfloat16 g_Sf[NM * NDI];        // silu(proj_fwd + bias) bf16
__device__ __nv_bfloat16 g_Y [NM * NDI];        // gated mixer output bf16
__device__ float  g_H [NM * ND];                // residual + out_proj (fp32)

__device__ __forceinline__ float silu_f(float x) {
    return x / (1.0f + __expf(-x));
}

__device__ __forceinline__ u32 smem_u32(const void* p) {
    u32 a;
    asm("{ .reg .u64 t; cvta.to.shared.u64 t, %1; cvt.u32.u64 %0, t; }"
        : "=r"(a) : "l"(p));
    return a;
}

// ---------------------------------------------------------------------------
// PTX primitives: cp.async, ldmatrix, mma (all compute_103-base legal)
// ---------------------------------------------------------------------------
__device__ __forceinline__ void cpa16(u32 s, const void* g) {
    asm volatile("cp.async.cg.shared.global [%0], [%1], 16;" :: "r"(s), "l"(g));
}
#define CP_COMMIT()  asm volatile("cp.async.commit_group;" ::: "memory")
#define CP_WAIT(N)   asm volatile("cp.async.wait_group %0;" :: "n"(N) : "memory")

#define LDSM4(r0, r1, r2, r3, addr) \
    asm volatile("ldmatrix.sync.aligned.m8n8.x4.shared.b16 {%0,%1,%2,%3}, [%4];" \
        : "=r"(r0), "=r"(r1), "=r"(r2), "=r"(r3) : "r"(addr))

#define MMA16816(c, a, b) \
    asm volatile("mma.sync.aligned.m16n8k16.row.col.f32.bf16.bf16.f32 " \
        "{%0,%1,%2,%3}, {%4,%5,%6,%7}, {%8,%9}, {%0,%1,%2,%3};" \
        : "+f"((c)[0]), "+f"((c)[1]), "+f"((c)[2]), "+f"((c)[3]) \
        : "r"((a)[0]), "r"((a)[1]), "r"((a)[2]), "r"((a)[3]), \
          "r"((b)[0]), "r"((b)[1]))

// ---------------------------------------------------------------------------
// Warp-MMA GEMM: C[m,n] = sum_k A[m,k]*W[n,k], bf16 in, fp32 accum.
// BM=BN=128, BK=64, 256 threads = 8 warps (2M x 4N), 64x32 warp tiles.
// SW128-swizzled smem, 3-stage cp.async pipeline, one barrier per slab.
// mode 0: split: tile n0 < NDI -> o0 (Xp), else o1 (Z)    [bf16]
// mode 1: o0[m,n] = bf16( silu(acc + bias[n]) )           [bf16]
// mode 2: of[m,n] = acc + resid[m,n]                      [fp32]
// mode 3: sb = silu(acc + bias[n]);  (combine fused)
//         y = (fm*Sf + bm*sb + Xp*diag) * silu(Z) * gs -> o0 (Y) [bf16]
// ---------------------------------------------------------------------------
#define GEMM_SMEM (1024 + 3 * 32768)

__global__ __launch_bounds__(256, 2)
void gemm_mma(const __nv_bfloat16* __restrict__ A, const __nv_bfloat16* __restrict__ W,
              int K, int mode,
              __nv_bfloat16* __restrict__ o0, __nv_bfloat16* __restrict__ o1,
              const float* __restrict__ bias, const float* __restrict__ resid,
              float* __restrict__ of, int Nout,
              const __nv_bfloat16* __restrict__ eSf, const __nv_bfloat16* __restrict__ eXp,
              const __nv_bfloat16* __restrict__ eZ,
              const float* __restrict__ diag, const float* __restrict__ gsp)
{
    extern __shared__ char dsm[];
    const u32 dyn  = smem_u32(dsm);
    const u32 base = (dyn + 1023u) & ~1023u;

    const int tid  = threadIdx.x;
    const int wid  = tid >> 5;
    const int lane = tid & 31;
    const int m0   = blockIdx.y << 7;
    const int n0   = blockIdx.x << 7;
    const int warp_m = wid >> 2;      // 0..1
    const int warp_n = wid & 3;       // 0..3

    // ---- cp.async assignments: 4 chunks of 16B per thread per tile ----
    int swoff[4];
    const __nv_bfloat16* gA[4];
    const __nv_bfloat16* gB[4];
#pragma unroll
    for (int i = 0; i < 4; ++i) {
        const int idx = i * 256 + tid;
        const int row = idx >> 3;
        const int ch  = idx & 7;
        swoff[i] = row * 128 + ((ch * 16) ^ ((row & 7) << 4));
        gA[i] = A + (size_t)(m0 + row) * K + ch * 8;
        gB[i] = W + (size_t)(n0 + row) * K + ch * 8;
    }

    // ---- ldmatrix per-lane address components ----
    const int blk = lane >> 3;        // 0..3
    const int lr  = lane & 7;
    int aRow[4], aXr[4];
#pragma unroll
    for (int mi = 0; mi < 4; ++mi) {
        const int r = warp_m * 64 + mi * 16 + (blk & 1) * 8 + lr;
        aRow[mi] = r * 128;
        aXr[mi]  = (r & 7) << 4;
    }
    const int koA = (blk >> 1) * 16;
    int bRow[2], bXr[2];
#pragma unroll
    for (int np = 0; np < 2; ++np) {
        const int r = warp_n * 32 + np * 16 + (blk >> 1) * 8 + lr;
        bRow[np] = r * 128;
        bXr[np]  = (r & 7) << 4;
    }
    const int koB = (blk & 1) * 16;

    float acc[4][4][4];
#pragma unroll
    for (int mi = 0; mi < 4; ++mi)
#pragma unroll
        for (int ni = 0; ni < 4; ++ni)
#pragma unroll
            for (int j = 0; j < 4; ++j) acc[mi][ni][j] = 0.0f;

    const int S = K >> 6;

    // ---- prologue: issue slabs 0 and 1 ----
#pragma unroll
    for (int i = 0; i < 4; ++i) {
        cpa16(base + swoff[i], gA[i]);
        cpa16(base + 16384u + swoff[i], gB[i]);
    }
    CP_COMMIT();
    if (S > 1) {
#pragma unroll
        for (int i = 0; i < 4; ++i) {
            cpa16(base + 32768u + swoff[i], gA[i] + 64);
            cpa16(base + 49152u + swoff[i], gB[i] + 64);
        }
    }
    CP_COMMIT();

    u32 ar = base;                 // read stage
    u32 aw = base + 2u * 32768u;   // write stage (stage 2 first)
    const u32 top = base + 3u * 32768u;

    for (int s = 0; s < S; ++s) {
        if (s < S - 1) { CP_WAIT(1); } else { CP_WAIT(0); }
        __syncthreads();

        if (s + 2 < S) {
            const int k0 = (s + 2) << 6;
#pragma unroll
            for (int i = 0; i < 4; ++i) {
                cpa16(aw + swoff[i], gA[i] + k0);
                cpa16(aw + 16384u + swoff[i], gB[i] + k0);
            }
            aw += 32768u; if (aw == top) aw = base;
        }
        CP_COMMIT();

        const u32 sa = ar;
        const u32 sb = ar + 16384u;
#pragma unroll
        for (int kk = 0; kk < 4; ++kk) {
            u32 a[4][4];
#pragma unroll
            for (int mi = 0; mi < 4; ++mi) {
                const u32 ad = sa + aRow[mi] + ((kk * 32 + koA) ^ aXr[mi]);
                LDSM4(a[mi][0], a[mi][1], a[mi][2], a[mi][3], ad);
            }
            u32 b[4][2];
#pragma unroll
            for (int np = 0; np < 2; ++np) {
                const u32 bd = sb + bRow[np] + ((kk * 32 + koB) ^ bXr[np]);
                LDSM4(b[2*np][0], b[2*np][1], b[2*np+1][0], b[2*np+1][1], bd);
            }
#pragma unroll
            for (int mi = 0; mi < 4; ++mi)
#pragma unroll
                for (int ni = 0; ni < 4; ++ni)
                    MMA16816(acc[mi][ni], a[mi], b[ni]);
        }
        ar += 32768u; if (ar == top) ar = base;
    }

    // ---- epilogue ----
    const int mrow0 = m0 + warp_m * 64 + (lane >> 2);
    const int ncol0 = n0 + warp_n * 32 + (lane & 3) * 2;

    if (mode == 2) {
#pragma unroll
        for (int mi = 0; mi < 4; ++mi) {
#pragma unroll
            for (int ni = 0; ni < 4; ++ni) {
                const int m = mrow0 + mi * 16;
                const int n = ncol0 + ni * 8;
                const float* c = acc[mi][ni];
                float2 r0 = *(const float2*)(resid + (size_t)m * Nout + n);
                float2 r1 = *(const float2*)(resid + (size_t)(m + 8) * Nout + n);
                float2 v0 = { c[0] + r0.x, c[1] + r0.y };
                float2 v1 = { c[2] + r1.x, c[3] + r1.y };
                *(float2*)(of + (size_t)m * Nout + n)       = v0;
                *(float2*)(of + (size_t)(m + 8) * Nout + n) = v1;
            }
        }
    } else if (mode == 3) {
        const float gs = gsp[0];
#pragma unroll
        for (int mi = 0; mi < 4; ++mi) {
            const int m  = mrow0 + mi * 16;
            const int t0 = m & (NT - 1);
            const int t1 = (m + 8) & (NT - 1);
            const float fm0 = (t0 > 0) ? 1.0f : 0.0f;
            const float bm0 = (t0 < NT - 1) ? 1.0f : 0.0f;
            const float fm1 = (t1 > 0) ? 1.0f : 0.0f;
            const float bm1 = (t1 < NT - 1) ? 1.0f : 0.0f;
#pragma unroll
            for (int ni = 0; ni < 4; ++ni) {
                const int n = ncol0 + ni * 8;
                const size_t o0i = (size_t)m * NDI + n;
                const size_t o1i = (size_t)(m + 8) * NDI + n;
                const float2 dg = *(const float2*)(diag + n);
                const float b0 = bias[n], b1 = bias[n + 1];

                __nv_bfloat162 sf0 = *(const __nv_bfloat162*)(eSf + o0i);
                __nv_bfloat162 sf1 = *(const __nv_bfloat162*)(eSf + o1i);
                __nv_bfloat162 xp0 = *(const __nv_bfloat162*)(eXp + o0i);
                __nv_bfloat162 xp1 = *(const __nv_bfloat162*)(eXp + o1i);
                __nv_bfloat162 z0  = *(const __nv_bfloat162*)(eZ  + o0i);
                __nv_bfloat162 z1  = *(const __nv_bfloat162*)(eZ  + o1i);

                const float sb00 = silu_f(acc[mi][ni][0] + b0);
                const float sb01 = silu_f(acc[mi][ni][1] + b1);
                const float sb10 = silu_f(acc[mi][ni][2] + b0);
                const float sb11 = silu_f(acc[mi][ni][3] + b1);

                float y00 = (fm0 * __bfloat162float(sf0.x) + bm0 * sb00 +
                             __bfloat162float(xp0.x) * dg.x) * silu_f(__bfloat162float(z0.x)) * gs;
                float y01 = (fm0 * __bfloat162float(sf0.y) + bm0 * sb01 +
                             __bfloat162float(xp0.y) * dg.y) * silu_f(__bfloat162float(z0.y)) * gs;
                float y10 = (fm1 * __bfloat162float(sf1.x) + bm1 * sb10 +
                             __bfloat162float(xp1.x) * dg.x) * silu_f(__bfloat162float(z1.x)) * gs;
                float y11 = (fm1 * __bfloat162float(sf1.y) + bm1 * sb11 +
                             __bfloat162float(xp1.y) * dg.y) * silu_f(__bfloat162float(z1.y)) * gs;

                __nv_bfloat162 h0, h1;
                h0.x = __float2bfloat16(y00); h0.y = __float2bfloat16(y01);
                h1.x = __float2bfloat16(y10); h1.y = __float2bfloat16(y11);
                *(u32*)(o0 + o0i) = *(u32*)&h0;
                *(u32*)(o0 + o1i) = *(u32*)&h1;
            }
        }
    } else {
        __nv_bfloat16* dst = o0;
        int nsub = 0;
        if (mode == 0 && n0 >= NDI) { dst = o1; nsub = NDI; }
#pragma unroll
        for (int mi = 0; mi < 4; ++mi) {
#pragma unroll
            for (int ni = 0; ni < 4; ++ni) {
                const int m = mrow0 + mi * 16;
                const int n = ncol0 + ni * 8;
                float c0 = acc[mi][ni][0], c1 = acc[mi][ni][1];
                float c2 = acc[mi][ni][2], c3 = acc[mi][ni][3];
                if (mode == 1) {
                    const float b0 = bias[n], b1 = bias[n + 1];
                    c0 = silu_f(c0 + b0); c1 = silu_f(c1 + b1);
                    c2 = silu_f(c2 + b0); c3 = silu_f(c3 + b1);
                }
                __nv_bfloat162 h0, h1;
                h0.x = __float2bfloat16(c0); h0.y = __float2bfloat16(c1);
                h1.x = __float2bfloat16(c2); h1.y = __float2bfloat16(c3);
                const int nl = n - nsub;
                *(u32*)(dst + (size_t)m * NDI + nl)       = *(u32*)&h0;
                *(u32*)(dst + (size_t)(m + 8) * NDI + nl) = *(u32*)&h1;
            }
        }
    }
}

// ---------------------------------------------------------------------------
// Fused prep: converts x, wi, wpf, wpb, wo fp32->bf16 in ONE kernel, plus
// conv weight transpose at the tail. One launch, streaming-friendly.
// Unit = 4 floats. Ranges (cumulative):
//   x   : [0,           4194304)
//   wi  : [4194304,     4456448)
//   wpf : [4456448,     4718592)
//   wpb : [4718592,     4980736)
//   wo  : [4980736,     5111808)
//   cw  : [5111808,     5113600)   (7*NDI/4 = 1792 units per direction)
// ---------------------------------------------------------------------------
#define U_X   (NM * ND / 4)                    // 4194304
#define U_WI  (U_X  + 2 * NDI * ND / 4)        // 4456448
#define U_WPF (U_WI + NDI * NDI / 4)           // 4718592
#define U_WPB (U_WPF + NDI * NDI / 4)          // 4980736
#define U_WO  (U_WPB + ND * NDI / 4)           // 5111808
#define U_CW  (U_WO + 7 * NDI / 4)             // 5113600

__global__ __launch_bounds__(256)
void prep_kernel(const float* __restrict__ x,   const float* __restrict__ wi,
                 const float* __restrict__ wpf, const float* __restrict__ wpb,
                 const float* __restrict__ wo,
                 const float* __restrict__ cwf, const float* __restrict__ cwb)
{
    const int i = blockIdx.x * blockDim.x + threadIdx.x;
    if (i >= U_CW) return;

    if (i < U_WO) {
        const float* src;
        __nv_bfloat16* dst;
        int off;
        if (i < U_X)        { src = x;   dst = g_xbf; off = i; }
        else if (i < U_WI)  { src = wi;  dst = g_wi;  off = i - U_X; }
        else if (i < U_WPF) { src = wpf; dst = g_wpf; off = i - U_WI; }
        else if (i < U_WPB) { src = wpb; dst = g_wpb; off = i - U_WPF; }
        else                { src = wo;  dst = g_wo;  off = i - U_WPB; }
        const float4 v = ((const float4*)src)[off];
        __nv_bfloat162 h0, h1;
        h0.x = __float2bfloat16(v.x); h0.y = __float2bfloat16(v.y);
        h1.x = __float2bfloat16(v.z); h1.y = __float2bfloat16(v.w);
        uint2 o;
        o.x = *(u32*)&h0; o.y = *(u32*)&h1;
        ((uint2*)dst)[off] = o;
    } else {
        // conv weight transpose: 4 elements per unit, both directions
        const int e0 = (i - U_WO) * 4;           // element index into 7*NDI
#pragma unroll
        for (int q = 0; q < 4; ++q) {
            const int e = e0 + q;
            const int j = e / NDI, c = e - j * NDI;
            g_cwf[e] = cwf[c * 7 + j];
            g_cwb[e] = cwb[c * 7 + j];
        }
    }
}

// ---------------------------------------------------------------------------
// Depthwise causal (fwd) + anti-causal (bwd) conv, smem-tiled.
// Tile: 128 t-rows x 64 channels; strip of 142 rows loaded once.
// ---------------------------------------------------------------------------
#define CT_M 128
#define CT_C 64

__device__ __forceinline__ void unpack8s(uint4 v, float* f) {
    __nv_bfloat162 h;
    h = *(__nv_bfloat162*)&v.x; f[0] = __bfloat162float(h.x); f[1] = __bfloat162float(h.y);
    h = *(__nv_bfloat162*)&v.y; f[2] = __bfloat162float(h.x); f[3] = __bfloat162float(h.y);
    h = *(__nv_bfloat162*)&v.z; f[4] = __bfloat162float(h.x); f[5] = __bfloat162float(h.y);
    h = *(__nv_bfloat162*)&v.w; f[6] = __bfloat162float(h.x); f[7] = __bfloat162float(h.y);
}

__device__ __forceinline__ uint4 pack8s(const float* f) {
    u32 pk[4];
#pragma unroll
    for (int j = 0; j < 4; ++j) {
        __nv_bfloat162 h;
        h.x = __float2bfloat16(f[2*j]);
        h.y = __float2bfloat16(f[2*j+1]);
        pk[j] = *(u32*)&h;
    }
    return *(uint4*)pk;
}

__global__ __launch_bounds__(256)
void conv_kernel(const float* __restrict__ bfc, const float* __restrict__ bbc)
{
    __shared__ __nv_bfloat16 sx[142][CT_C];
    __shared__ float swf[7][CT_C], swb[7][CT_C];
    __shared__ float sbf[CT_C], sbb[CT_C];

    const int c0  = blockIdx.x * CT_C;
    const int m0  = blockIdx.y * CT_M;
    const int lo  = m0 & ~(NT - 1);        // batch start row
    const int hi  = lo + NT;
    const int tid = threadIdx.x;

    // weights -> smem (fp32)
    if (tid < 7 * CT_C / 8) {              // 56 threads, 8 ch each
        const int j = tid >> 3, cc = (tid & 7) * 8;
        *(float4*)&swf[j][cc]     = *(const float4*)(g_cwf + j * NDI + c0 + cc);
        *(float4*)&swf[j][cc + 4] = *(const float4*)(g_cwf + j * NDI + c0 + cc + 4);
        *(float4*)&swb[j][cc]     = *(const float4*)(g_cwb + j * NDI + c0 + cc);
        *(float4*)&swb[j][cc + 4] = *(const float4*)(g_cwb + j * NDI + c0 + cc + 4);
    }
    if (tid >= 64 && tid < 64 + CT_C / 4) {
        const int q = (tid - 64) * 4;
        *(float4*)&sbf[q] = *(const float4*)(bfc + c0 + q);
        *(float4*)&sbb[q] = *(const float4*)(bbc + c0 + q);
    }

    // Xp strip: rows m0-7 .. m0+134, zero outside batch
    for (int u = tid; u < 142 * 8; u += 256) {
        const int r = u >> 3, cc = (u & 7) * 8;
        const int m = m0 - 7 + r;
        uint4 v = make_uint4(0, 0, 0, 0);
        if (m >= lo && m < hi)
            v = *(const uint4*)(g_Xp + (size_t)m * NDI + c0 + cc);
        *(uint4*)&sx[r][cc] = v;
    }
    __syncthreads();

    // compute: 128 rows x 8 units of 8 channels
    for (int u = tid; u < CT_M * 8; u += 256) {
        const int r  = u >> 3, cc = (u & 7) * 8;
        const int m  = m0 + r;
        float accf[8], accb[8];
#pragma unroll
        for (int q = 0; q < 8; ++q) { accf[q] = sbf[cc + q]; accb[q] = sbb[cc + q]; }
#pragma unroll
        for (int k = 0; k < 7; ++k) {
            float xf[8], xb[8];
            unpack8s(*(const uint4*)&sx[r + k][cc], xf);          // Xp[m-7+k]
            unpack8s(*(const uint4*)&sx[r + 14 - k][cc], xb);     // Xp[m+7-k]
#pragma unroll
            for (int q = 0; q < 8; ++q) {
                accf[q] = fmaf(swf[k][cc + q], xf[q], accf[q]);
                accb[q] = fmaf(swb[k][cc + q], xb[q], accb[q]);
            }
        }
        const size_t o = (size_t)m * NDI + c0 + cc;
        *(uint4*)(g_Af + o) = pack8s(accf);
        *(uint4*)(g_Ab + o) = pack8s(accb);
    }
}

// ---------------------------------------------------------------------------
// LayerNorm over last dim (512), one block (128 threads) per row.
// ---------------------------------------------------------------------------
__global__ void ln_kernel(const float* __restrict__ lng, const float* __restrict__ lnb,
                          float* __restrict__ out)
{
    const int row = blockIdx.x;
    const int tid = threadIdx.x;                 // 0..127

    const float4 v = ((const float4*)(g_H + (size_t)row * ND))[tid];
    float s  = v.x + v.y + v.z + v.w;
    float ss = v.x*v.x + v.y*v.y + v.z*v.z + v.w*v.w;

#pragma unroll
    for (int o = 16; o > 0; o >>= 1) {
        s  += __shfl_xor_sync(0xffffffffu, s,  o);
        ss += __shfl_xor_sync(0xffffffffu, ss, o);
    }
    __shared__ float shs[4], shss[4];
    if ((tid & 31) == 0) { shs[tid >> 5] = s; shss[tid >> 5] = ss; }
    __syncthreads();
    s  = shs[0]  + shs[1]  + shs[2]  + shs[3];
    ss = shss[0] + shss[1] + shss[2] + shss[3];

    const float mu  = s * (1.0f / ND);
    const float var = ss * (1.0f / ND) - mu * mu;
    const float inv = rsqrtf(var + 1e-5f);

    const float4 g4 = ((const float4*)lng)[tid];
    const float4 b4 = ((const float4*)lnb)[tid];
    float4 o4;
    o4.x = (v.x - mu) * inv * g4.x + b4.x;
    o4.y = (v.y - mu) * inv * g4.y + b4.y;
    o4.z = (v.z - mu) * inv * g4.z + b4.z;
    o4.w = (v.w - mu) * inv * g4.w + b4.w;
    ((float4*)(out + (size_t)row * ND))[tid] = o4;
}

// ---------------------------------------------------------------------------
// Launch
// ---------------------------------------------------------------------------
extern "C" void kernel_launch(void* const* d_in, const int* in_sizes, int n_in,
                              void* d_out, int out_size)
{
    const float* x    = (const float*)d_in[0];   // (B,T,D)
    const float* winp = (const float*)d_in[1];   // (2*DI, D)
    const float* wcf  = (const float*)d_in[2];   // (DI,1,K)
    const float* bcf  = (const float*)d_in[3];   // (DI,)
    const float* wpf  = (const float*)d_in[4];   // (DI,DI)
    const float* bpf  = (const float*)d_in[5];   // (DI,)
    const float* wcb  = (const float*)d_in[6];
    const float* bcb  = (const float*)d_in[7];
    const float* wpb  = (const float*)d_in[8];
    const float* bpb  = (const float*)d_in[9];
    const float* diag = (const float*)d_in[10];  // (DI,)
    const float* gsc  = (const float*)d_in[11];  // (1,)
    const float* wout = (const float*)d_in[12];  // (D, DI)
    const float* lng  = (const float*)d_in[13];  // (D,)
    const float* lnb  = (const float*)d_in[14];  // (D,)
    float* out = (float*)d_out;

    __nv_bfloat16 *pxbf, *pwi, *pwpf, *pwpb, *pwo;
    __nv_bfloat16 *pXp, *pZ, *pAf, *pAb, *pSf, *pY;
    float *pH;
    cudaGetSymbolAddress((void**)&pxbf, g_xbf);
    cudaGetSymbolAddress((void**)&pwi,  g_wi);
    cudaGetSymbolAddress((void**)&pwpf, g_wpf);
    cudaGetSymbolAddress((void**)&pwpb, g_wpb);
    cudaGetSymbolAddress((void**)&pwo,  g_wo);
    cudaGetSymbolAddress((void**)&pXp,  g_Xp);
    cudaGetSymbolAddress((void**)&pZ,   g_Z);
    cudaGetSymbolAddress((void**)&pAf,  g_Af);
    cudaGetSymbolAddress((void**)&pAb,  g_Ab);
    cudaGetSymbolAddress((void**)&pSf,  g_Sf);
    cudaGetSymbolAddress((void**)&pY,   g_Y);
    cudaGetSymbolAddress((void**)&pH,   g_H);

    cudaFuncSetAttribute(gemm_mma, cudaFuncAttributeMaxDynamicSharedMemorySize, GEMM_SMEM);

    // 0) all fp32->bf16 conversions + conv weight transpose in ONE launch
    prep_kernel<<<(U_CW + 255) / 256, 256>>>(x, winp, wpf, wpb, wout, wcf, wcb);

    // 1) in_proj: split into Xp, Z (bf16)
    gemm_mma<<<dim3(2 * NDI / 128, NM / 128), 256, GEMM_SMEM>>>(
        pxbf, pwi, ND, 0, pXp, pZ, nullptr, nullptr, nullptr, 2 * NDI,
        nullptr, nullptr, nullptr, nullptr, nullptr);

    // 2) depthwise convs -> Af, Ab (bf16)
    conv_kernel<<<dim3(NDI / CT_C, NM / CT_M), 256>>>(bcf, bcb);

    // 3) fwd proj with fused bias + silu -> Sf (bf16)
    gemm_mma<<<dim3(NDI / 128, NM / 128), 256, GEMM_SMEM>>>(
        pAf, pwpf, NDI, 1, pSf, nullptr, bpf, nullptr, nullptr, NDI,
        nullptr, nullptr, nullptr, nullptr, nullptr);

    // 4) bwd proj with fused bias + silu + combine + gate -> Y (bf16)
    gemm_mma<<<dim3(NDI / 128, NM / 128), 256, GEMM_SMEM>>>(
        pAb, pwpb, NDI, 3, pY, nullptr, bpb, nullptr, nullptr, NDI,
        pSf, pXp, pZ, diag, gsc);

    // 5) out_proj + residual -> H (fp32)
    gemm_mma<<<dim3(ND / 128, NM / 128), 256, GEMM_SMEM>>>(
        pY, pwo, NDI, 2, nullptr, nullptr, nullptr, x, pH, ND,
        nullptr, nullptr, nullptr, nullptr, nullptr);

    // 6) LayerNorm -> out
    ln_kernel<<<NM, 128>>>(lng, lnb, out);
}